// round 3
// baseline (speedup 1.0000x reference)
#include <cuda_runtime.h>
#include <math.h>

// Problem shapes (fixed by the dataset)
#define N_Q 256      // queries
#define DIM 512      // feature dim
#define QB  2048     // bank size
#define NC  1000     // classes
#define IMG 150528   // 3*224*224
#define IMG4 (IMG/4) // 37632 float4 per image
#define KNN 4

// Output layout (float32, concatenated in reference return order)
#define OFF_LBL 0
#define OFF_PRB 256
#define OFF_IMG 256256           // 256 + 256*1000
#define OFF_GRD 38791424         // OFF_IMG + 256*150528

// Scratch (static device globals — no allocations allowed)
__device__ float g_qinv[N_Q];
__device__ float g_binv[QB];
__device__ float g_dist[(size_t)N_Q * QB];
__device__ int   g_idx[N_Q * KNN];

// ---------------------------------------------------------------------------
// K0: inverse L2 norms for query rows and bank rows (ONE WARP per row)
// ---------------------------------------------------------------------------
__global__ void norms_kernel(const float* __restrict__ feat,
                             const float* __restrict__ bank) {
    int w    = (blockIdx.x * blockDim.x + threadIdx.x) >> 5;
    int lane = threadIdx.x & 31;
    if (w >= N_Q + QB) return;
    const float* row = (w < N_Q) ? feat + (size_t)w * DIM
                                 : bank + (size_t)(w - N_Q) * DIM;
    const float4* r4 = (const float4*)row;
    float s = 0.f;
#pragma unroll
    for (int i = 0; i < 4; i++) {
        float4 v = r4[lane + 32 * i];
        s += v.x * v.x + v.y * v.y + v.z * v.z + v.w * v.w;
    }
#pragma unroll
    for (int o = 16; o; o >>= 1) s += __shfl_xor_sync(0xffffffffu, s, o);
    if (lane == 0) {
        float inv = 1.0f / fmaxf(sqrtf(s), 1e-12f);
        if (w < N_Q) g_qinv[w] = inv;
        else         g_binv[w - N_Q] = inv;
    }
}

// ---------------------------------------------------------------------------
// K1: distance matrix D[q][b] = 1 - dot(q,b)*qinv*binv
// Register-tiled SGEMM: 64x64x32 block tile, 4x4 per thread, 256 threads.
// grid = (QB/64, N_Q/64) = (32, 4) = 128 CTAs
// ---------------------------------------------------------------------------
#define BM 64
#define BN 64
#define BK 32
__global__ void dist_kernel(const float* __restrict__ A,   // features  (N_Q,DIM)
                            const float* __restrict__ B) { // bank      (QB,DIM)
    __shared__ float As[BK][BM];
    __shared__ float Bs[BK][BN];
    int tid = threadIdx.x;
    int tx = tid & 15;        // 0..15  -> bank micro-tile
    int ty = tid >> 4;        // 0..15  -> query micro-tile
    int qb = blockIdx.y * BM;
    int bb = blockIdx.x * BN;

    float acc[4][4] = {};

    for (int k0 = 0; k0 < DIM; k0 += BK) {
        // Each tile: 64 rows x 32 cols = 512 float4; 2 per thread.
#pragma unroll
        for (int l = 0; l < 2; l++) {
            int i  = tid + l * 256;   // float4 index 0..511
            int r  = i >> 3;          // row in tile 0..63
            int c4 = i & 7;           // float4 col 0..7
            float4 v = *(const float4*)(A + (size_t)(qb + r) * DIM + k0 + c4 * 4);
            As[c4 * 4 + 0][r] = v.x; As[c4 * 4 + 1][r] = v.y;
            As[c4 * 4 + 2][r] = v.z; As[c4 * 4 + 3][r] = v.w;
            float4 w = *(const float4*)(B + (size_t)(bb + r) * DIM + k0 + c4 * 4);
            Bs[c4 * 4 + 0][r] = w.x; Bs[c4 * 4 + 1][r] = w.y;
            Bs[c4 * 4 + 2][r] = w.z; Bs[c4 * 4 + 3][r] = w.w;
        }
        __syncthreads();
#pragma unroll
        for (int k = 0; k < BK; k++) {
            float ra[4], rb[4];
#pragma unroll
            for (int i = 0; i < 4; i++) ra[i] = As[k][ty * 4 + i];
#pragma unroll
            for (int j = 0; j < 4; j++) rb[j] = Bs[k][tx * 4 + j];
#pragma unroll
            for (int i = 0; i < 4; i++)
#pragma unroll
                for (int j = 0; j < 4; j++)
                    acc[i][j] = fmaf(ra[i], rb[j], acc[i][j]);
        }
        __syncthreads();
    }

#pragma unroll
    for (int i = 0; i < 4; i++) {
        int q = qb + ty * 4 + i;
        float qi = g_qinv[q];
#pragma unroll
        for (int j = 0; j < 4; j++) {
            int b = bb + tx * 4 + j;
            g_dist[(size_t)q * QB + b] = 1.0f - acc[i][j] * qi * g_binv[b];
        }
    }
}

// ---------------------------------------------------------------------------
// K2: top-4 largest distances per query. Tie-break: smaller index wins
// (matches lax.top_k stability). One block per query, 128 threads.
// ---------------------------------------------------------------------------
__device__ __forceinline__ bool d_better(float v, int j, float v2, int j2) {
    return (v > v2) || (v == v2 && j < j2);
}
__device__ __forceinline__ void d_insert(float v, int j, float* bv, int* bi) {
    if (!d_better(v, j, bv[3], bi[3])) return;
    int p = 3;
    while (p > 0 && d_better(v, j, bv[p - 1], bi[p - 1])) {
        bv[p] = bv[p - 1]; bi[p] = bi[p - 1]; p--;
    }
    bv[p] = v; bi[p] = j;
}

__global__ void topk_kernel() {
    int q = blockIdx.x;
    int tid = threadIdx.x;   // 128 threads
    const float* dr = g_dist + (size_t)q * QB;

    float bv[4] = {-3.0e38f, -3.0e38f, -3.0e38f, -3.0e38f};
    int   bi[4] = {0x7fffffff, 0x7fffffff, 0x7fffffff, 0x7fffffff};
    int base = tid * (QB / 128);
#pragma unroll 4
    for (int e = 0; e < QB / 128; e++) {
        int j = base + e;
        d_insert(dr[j], j, bv, bi);
    }

    __shared__ float sv[128 * 4];
    __shared__ int   si[128 * 4];
#pragma unroll
    for (int k = 0; k < 4; k++) { sv[tid * 4 + k] = bv[k]; si[tid * 4 + k] = bi[k]; }
    __syncthreads();

    if (tid == 0) {
        float fv[4] = {-3.0e38f, -3.0e38f, -3.0e38f, -3.0e38f};
        int   fi[4] = {0x7fffffff, 0x7fffffff, 0x7fffffff, 0x7fffffff};
        for (int t = 0; t < 128 * 4; t++) d_insert(sv[t], si[t], fv, fi);
#pragma unroll
        for (int k = 0; k < 4; k++) g_idx[q * 4 + k] = fi[k];
    }
}

// ---------------------------------------------------------------------------
// K3: grads_m, pred_probs, pred_labels. One block per query, 256 threads.
// ---------------------------------------------------------------------------
__global__ void small_outputs_kernel(const float* __restrict__ bank,
                                     const float* __restrict__ probs,
                                     float* __restrict__ out) {
    int q = blockIdx.x, tid = threadIdx.x;
    __shared__ int ix[4];
    if (tid < 4) ix[tid] = g_idx[q * 4 + tid];
    __syncthreads();

    const float* b0 = bank + (size_t)ix[0] * DIM;
    const float* b1 = bank + (size_t)ix[1] * DIM;
    const float* b2 = bank + (size_t)ix[2] * DIM;
    const float* b3 = bank + (size_t)ix[3] * DIM;
    float* og = out + OFF_GRD + (size_t)q * DIM;
    for (int d = tid; d < DIM; d += 256)
        og[d] = 0.25f * (b0[d] + b1[d] + b2[d] + b3[d]);

    const float* p0 = probs + (size_t)ix[0] * NC;
    const float* p1 = probs + (size_t)ix[1] * NC;
    const float* p2 = probs + (size_t)ix[2] * NC;
    const float* p3 = probs + (size_t)ix[3] * NC;
    float* op = out + OFF_PRB + (size_t)q * NC;
    float bestv = -3.0e38f; int bestc = 0x7fffffff;
    for (int c = tid; c < NC; c += 256) {
        float m = 0.25f * (p0[c] + p1[c] + p2[c] + p3[c]);
        op[c] = m;
        if (m > bestv || (m == bestv && c < bestc)) { bestv = m; bestc = c; }
    }
    __shared__ float rv[256];
    __shared__ int   rc[256];
    rv[tid] = bestv; rc[tid] = bestc;
    __syncthreads();
    for (int s = 128; s; s >>= 1) {
        if (tid < s) {
            float v2 = rv[tid + s]; int c2 = rc[tid + s];
            if (v2 > rv[tid] || (v2 == rv[tid] && c2 < rc[tid])) {
                rv[tid] = v2; rc[tid] = c2;
            }
        }
        __syncthreads();
    }
    if (tid == 0) out[OFF_LBL + q] = (float)rc[0];
}

// ---------------------------------------------------------------------------
// K4: pred_images = mean of 4 gathered image rows. HBM-bound (~770 MB).
// grid = (256 queries, 21 chunks), 256 threads, float4, 7 iters/thread.
// ---------------------------------------------------------------------------
__global__ void images_kernel(const float* __restrict__ img,
                              float* __restrict__ out) {
    int q = blockIdx.x;
    __shared__ int ix[4];
    if (threadIdx.x < 4) ix[threadIdx.x] = g_idx[q * 4 + threadIdx.x];
    __syncthreads();

    const float4* im = (const float4*)img;
    float4* o = (float4*)(out + OFF_IMG) + (size_t)q * IMG4;
    size_t r0 = (size_t)ix[0] * IMG4;
    size_t r1 = (size_t)ix[1] * IMG4;
    size_t r2 = (size_t)ix[2] * IMG4;
    size_t r3 = (size_t)ix[3] * IMG4;

#pragma unroll
    for (int t = 0; t < 7; t++) {
        int f = blockIdx.y * 1792 + t * 256 + threadIdx.x;  // 21*1792 = 37632 = IMG4
        float4 a = im[r0 + f];
        float4 b = im[r1 + f];
        float4 c = im[r2 + f];
        float4 d = im[r3 + f];
        float4 r;
        r.x = 0.25f * (a.x + b.x + c.x + d.x);
        r.y = 0.25f * (a.y + b.y + c.y + d.y);
        r.z = 0.25f * (a.z + b.z + c.z + d.z);
        r.w = 0.25f * (a.w + b.w + c.w + d.w);
        o[f] = r;
    }
}

// ---------------------------------------------------------------------------
extern "C" void kernel_launch(void* const* d_in, const int* in_sizes, int n_in,
                              void* d_out, int out_size) {
    const float* feat  = (const float*)d_in[0];
    const float* bank  = (const float*)d_in[1];
    const float* probs = (const float*)d_in[2];
    const float* img   = (const float*)d_in[3];
    float* out = (float*)d_out;

    // one WARP per row: (N_Q+QB) warps = (N_Q+QB)*32 threads
    norms_kernel<<<((N_Q + QB) * 32 + 255) / 256, 256>>>(feat, bank);
    dist_kernel<<<dim3(QB / BN, N_Q / BM), 256>>>(feat, bank);
    topk_kernel<<<N_Q, 128>>>();
    small_outputs_kernel<<<N_Q, 256>>>(bank, probs, out);
    images_kernel<<<dim3(N_Q, 21), 256>>>(img, out);
}

// round 4
// speedup vs baseline: 1.0767x; 1.0767x over previous
#include <cuda_runtime.h>
#include <math.h>

// Problem shapes (fixed by the dataset)
#define N_Q 256      // queries
#define DIM 512      // feature dim
#define QB  2048     // bank size
#define NC  1000     // classes
#define IMG 150528   // 3*224*224
#define IMG4 (IMG/4) // 37632 float4 per image
#define KNN 4

// Output layout (float32, concatenated in reference return order)
#define OFF_LBL 0
#define OFF_PRB 256
#define OFF_IMG 256256           // 256 + 256*1000
#define OFF_GRD 38791424         // OFF_IMG + 256*150528

// Scratch (static device globals — no allocations allowed)
__device__ float g_qinv[N_Q];
__device__ float g_binv[QB];
__device__ float g_dist[(size_t)N_Q * QB];
__device__ int   g_idx[N_Q * KNN];

// ---------------------------------------------------------------------------
// K0: inverse L2 norms for query rows and bank rows (ONE WARP per row)
// ---------------------------------------------------------------------------
__global__ void norms_kernel(const float* __restrict__ feat,
                             const float* __restrict__ bank) {
    int w    = (blockIdx.x * blockDim.x + threadIdx.x) >> 5;
    int lane = threadIdx.x & 31;
    if (w >= N_Q + QB) return;
    const float* row = (w < N_Q) ? feat + (size_t)w * DIM
                                 : bank + (size_t)(w - N_Q) * DIM;
    const float4* r4 = (const float4*)row;
    float s = 0.f;
#pragma unroll
    for (int i = 0; i < 4; i++) {
        float4 v = r4[lane + 32 * i];
        s += v.x * v.x + v.y * v.y + v.z * v.z + v.w * v.w;
    }
#pragma unroll
    for (int o = 16; o; o >>= 1) s += __shfl_xor_sync(0xffffffffu, s, o);
    if (lane == 0) {
        float inv = 1.0f / fmaxf(sqrtf(s), 1e-12f);
        if (w < N_Q) g_qinv[w] = inv;
        else         g_binv[w - N_Q] = inv;
    }
}

// ---------------------------------------------------------------------------
// K1: distance matrix D[q][b] = 1 - dot(q,b)*qinv*binv
// Register-tiled SGEMM: 64x64x32 block tile, 4x4 per thread, 256 threads.
// ---------------------------------------------------------------------------
#define BM 64
#define BN 64
#define BK 32
__global__ void dist_kernel(const float* __restrict__ A,   // features  (N_Q,DIM)
                            const float* __restrict__ B) { // bank      (QB,DIM)
    __shared__ float As[BK][BM];
    __shared__ float Bs[BK][BN];
    int tid = threadIdx.x;
    int tx = tid & 15;
    int ty = tid >> 4;
    int qb = blockIdx.y * BM;
    int bb = blockIdx.x * BN;

    float acc[4][4] = {};

    for (int k0 = 0; k0 < DIM; k0 += BK) {
#pragma unroll
        for (int l = 0; l < 2; l++) {
            int i  = tid + l * 256;
            int r  = i >> 3;
            int c4 = i & 7;
            float4 v = *(const float4*)(A + (size_t)(qb + r) * DIM + k0 + c4 * 4);
            As[c4 * 4 + 0][r] = v.x; As[c4 * 4 + 1][r] = v.y;
            As[c4 * 4 + 2][r] = v.z; As[c4 * 4 + 3][r] = v.w;
            float4 w = *(const float4*)(B + (size_t)(bb + r) * DIM + k0 + c4 * 4);
            Bs[c4 * 4 + 0][r] = w.x; Bs[c4 * 4 + 1][r] = w.y;
            Bs[c4 * 4 + 2][r] = w.z; Bs[c4 * 4 + 3][r] = w.w;
        }
        __syncthreads();
#pragma unroll
        for (int k = 0; k < BK; k++) {
            float ra[4], rb[4];
#pragma unroll
            for (int i = 0; i < 4; i++) ra[i] = As[k][ty * 4 + i];
#pragma unroll
            for (int j = 0; j < 4; j++) rb[j] = Bs[k][tx * 4 + j];
#pragma unroll
            for (int i = 0; i < 4; i++)
#pragma unroll
                for (int j = 0; j < 4; j++)
                    acc[i][j] = fmaf(ra[i], rb[j], acc[i][j]);
        }
        __syncthreads();
    }

#pragma unroll
    for (int i = 0; i < 4; i++) {
        int q = qb + ty * 4 + i;
        float qi = g_qinv[q];
#pragma unroll
        for (int j = 0; j < 4; j++) {
            int b = bb + tx * 4 + j;
            g_dist[(size_t)q * QB + b] = 1.0f - acc[i][j] * qi * g_binv[b];
        }
    }
}

// ---------------------------------------------------------------------------
// K2: top-4 largest per query, tie-break smaller index (lax.top_k order).
// 256 threads/block, warp-shuffle butterfly merges (no serial reduction).
// ---------------------------------------------------------------------------
__device__ __forceinline__ bool d_better(float v, int j, float v2, int j2) {
    return (v > v2) || (v == v2 && j < j2);
}
__device__ __forceinline__ void d_insert(float v, int j, float* bv, int* bi) {
    if (!d_better(v, j, bv[3], bi[3])) return;
    int p = 3;
    while (p > 0 && d_better(v, j, bv[p - 1], bi[p - 1])) {
        bv[p] = bv[p - 1]; bi[p] = bi[p - 1]; p--;
    }
    bv[p] = v; bi[p] = j;
}
__device__ __forceinline__ void warp_merge_top4(float* bv, int* bi) {
#pragma unroll
    for (int o = 16; o; o >>= 1) {
        float pv[4]; int pi[4];
#pragma unroll
        for (int k = 0; k < 4; k++) {
            pv[k] = __shfl_xor_sync(0xffffffffu, bv[k], o);
            pi[k] = __shfl_xor_sync(0xffffffffu, bi[k], o);
        }
#pragma unroll
        for (int k = 0; k < 4; k++) d_insert(pv[k], pi[k], bv, bi);
    }
}

__global__ void topk_kernel() {
    int q = blockIdx.x;
    int tid = threadIdx.x;         // 256 threads
    int lane = tid & 31, wid = tid >> 5;
    const float4* dr = (const float4*)(g_dist + (size_t)q * QB);

    float bv[4] = {-3.0e38f, -3.0e38f, -3.0e38f, -3.0e38f};
    int   bi[4] = {0x7fffffff, 0x7fffffff, 0x7fffffff, 0x7fffffff};
#pragma unroll
    for (int l = 0; l < 2; l++) {
        int f = tid * 2 + l;       // float4 index, 512 total
        float4 v = dr[f];
        int j = f * 4;
        d_insert(v.x, j + 0, bv, bi);
        d_insert(v.y, j + 1, bv, bi);
        d_insert(v.z, j + 2, bv, bi);
        d_insert(v.w, j + 3, bv, bi);
    }
    warp_merge_top4(bv, bi);       // all lanes now hold warp top-4

    __shared__ float sv[32];
    __shared__ int   si[32];
    if (lane < 4) { sv[wid * 4 + lane] = bv[lane]; si[wid * 4 + lane] = bi[lane]; }
    __syncthreads();

    if (wid == 0) {
        float fv[4] = {-3.0e38f, -3.0e38f, -3.0e38f, -3.0e38f};
        int   fi[4] = {0x7fffffff, 0x7fffffff, 0x7fffffff, 0x7fffffff};
        d_insert(sv[lane], si[lane], fv, fi);   // 32 candidates, one per lane
        warp_merge_top4(fv, fi);
        if (lane < 4) g_idx[q * 4 + lane] = fi[lane];
    }
}

// ---------------------------------------------------------------------------
// K3: fused gather. grid=(256, 22), 256 threads.
//   blockIdx.y < 21 : pred_images chunk (HBM-bound bulk)
//   blockIdx.y ==21 : grads_m + pred_probs + pred_labels (latency-bound, hides
//                     inside the image gather wave)
// ---------------------------------------------------------------------------
__global__ void gather_kernel(const float* __restrict__ img,
                              const float* __restrict__ bank,
                              const float* __restrict__ probs,
                              float* __restrict__ out) {
    int q = blockIdx.x;
    int tid = threadIdx.x;
    __shared__ int ix[4];
    if (tid < 4) ix[tid] = g_idx[q * 4 + tid];
    __syncthreads();

    if (blockIdx.y < 21) {
        // ---- images slice ----
        const float4* im = (const float4*)img;
        float4* o = (float4*)(out + OFF_IMG) + (size_t)q * IMG4;
        size_t r0 = (size_t)ix[0] * IMG4;
        size_t r1 = (size_t)ix[1] * IMG4;
        size_t r2 = (size_t)ix[2] * IMG4;
        size_t r3 = (size_t)ix[3] * IMG4;
#pragma unroll
        for (int t = 0; t < 7; t++) {
            int f = blockIdx.y * 1792 + t * 256 + tid;   // 21*1792 = 37632 = IMG4
            float4 a = im[r0 + f];
            float4 b = im[r1 + f];
            float4 c = im[r2 + f];
            float4 d = im[r3 + f];
            float4 r;
            r.x = 0.25f * (a.x + b.x + c.x + d.x);
            r.y = 0.25f * (a.y + b.y + c.y + d.y);
            r.z = 0.25f * (a.z + b.z + c.z + d.z);
            r.w = 0.25f * (a.w + b.w + c.w + d.w);
            __stcs(&o[f], r);   // streaming store: no reuse of output
        }
        return;
    }

    // ---- small outputs slice ----
    // grads_m: 512 floats = 128 float4 -> threads 0..127
    if (tid < 128) {
        const float4* b0 = (const float4*)(bank + (size_t)ix[0] * DIM);
        const float4* b1 = (const float4*)(bank + (size_t)ix[1] * DIM);
        const float4* b2 = (const float4*)(bank + (size_t)ix[2] * DIM);
        const float4* b3 = (const float4*)(bank + (size_t)ix[3] * DIM);
        float4 a = b0[tid], b = b1[tid], c = b2[tid], d = b3[tid];
        float4 r;
        r.x = 0.25f * (a.x + b.x + c.x + d.x);
        r.y = 0.25f * (a.y + b.y + c.y + d.y);
        r.z = 0.25f * (a.z + b.z + c.z + d.z);
        r.w = 0.25f * (a.w + b.w + c.w + d.w);
        ((float4*)(out + OFF_GRD + (size_t)q * DIM))[tid] = r;
    }

    // pred_probs: 1000 floats = 250 float4 -> threads 0..249; then argmax
    float bestv = -3.0e38f;
    int   bestc = 0x7fffffff;
    if (tid < 250) {
        const float4* p0 = (const float4*)(probs + (size_t)ix[0] * NC);
        const float4* p1 = (const float4*)(probs + (size_t)ix[1] * NC);
        const float4* p2 = (const float4*)(probs + (size_t)ix[2] * NC);
        const float4* p3 = (const float4*)(probs + (size_t)ix[3] * NC);
        float4 a = p0[tid], b = p1[tid], c = p2[tid], d = p3[tid];
        float4 m;
        m.x = 0.25f * (a.x + b.x + c.x + d.x);
        m.y = 0.25f * (a.y + b.y + c.y + d.y);
        m.z = 0.25f * (a.z + b.z + c.z + d.z);
        m.w = 0.25f * (a.w + b.w + c.w + d.w);
        ((float4*)(out + OFF_PRB + (size_t)q * NC))[tid] = m;
        int c0 = tid * 4;
        // element-order argmax with smaller-index tie-break
        bestv = m.x; bestc = c0;
        if (m.y > bestv) { bestv = m.y; bestc = c0 + 1; }
        if (m.z > bestv) { bestv = m.z; bestc = c0 + 2; }
        if (m.w > bestv) { bestv = m.w; bestc = c0 + 3; }
    }
    // block argmax reduction (tie: smaller class index)
    __shared__ float rv[256];
    __shared__ int   rc[256];
    rv[tid] = bestv; rc[tid] = bestc;
    __syncthreads();
    for (int s = 128; s; s >>= 1) {
        if (tid < s) {
            float v2 = rv[tid + s]; int c2 = rc[tid + s];
            if (v2 > rv[tid] || (v2 == rv[tid] && c2 < rc[tid])) {
                rv[tid] = v2; rc[tid] = c2;
            }
        }
        __syncthreads();
    }
    if (tid == 0) out[OFF_LBL + q] = (float)rc[0];
}

// ---------------------------------------------------------------------------
extern "C" void kernel_launch(void* const* d_in, const int* in_sizes, int n_in,
                              void* d_out, int out_size) {
    const float* feat  = (const float*)d_in[0];
    const float* bank  = (const float*)d_in[1];
    const float* probs = (const float*)d_in[2];
    const float* img   = (const float*)d_in[3];
    float* out = (float*)d_out;

    norms_kernel<<<((N_Q + QB) * 32 + 255) / 256, 256>>>(feat, bank);
    dist_kernel<<<dim3(QB / BN, N_Q / BM), 256>>>(feat, bank);
    topk_kernel<<<N_Q, 256>>>();
    gather_kernel<<<dim3(N_Q, 22), 256>>>(img, bank, probs, out);
}